// round 1
// baseline (speedup 1.0000x reference)
#include <cuda_runtime.h>
#include <cuda_fp16.h>
#include <cstdint>

// ---------------- problem constants ----------------
#define NLVL   16
#define TSZ    (1u << 19)          // hashmap entries per level
#define HID    128
#define NPTS   (1u << 20)
#define TILE_M 128
#define NTILES (NPTS / TILE_M)     // 8192
#define PRIME_Y 2654435761u

// per-level resolutions: floor(16 * (128^(1/15))^l), verified in float64
__device__ __constant__ float c_res[NLVL] = {
    16.f, 22.f, 30.f, 42.f, 58.f, 80.f, 111.f, 153.f,
    212.f, 294.f, 406.f, 561.f, 776.f, 1072.f, 1482.f, 2048.f
};

// ---------------- smem layout ----------------
// strides padded (+8 halfs = 16B) so ldmatrix row addresses are conflict-free
struct __align__(16) Smem {
    __half W0[32][136];     // 8704 B   (K=32  x N=128)
    __half W1[128][136];    // 34816 B
    __half W2[128][136];    // 34816 B
    __half W3[128][8];      // 2048 B   (cols 3..7 zero-padded)
    float  b0[128];
    float  b1[128];
    float  b2[128];
    float  b3[4];
    __half A [128][40];     // encoded features, K=32 (+8 pad)
    __half Ha[128][136];
    __half Hb[128][136];
};                           // total 161808 B

// ---------------- ptx helpers ----------------
__device__ __forceinline__ unsigned smem_u32(const void* p) {
    return (unsigned)__cvta_generic_to_shared(p);
}
__device__ __forceinline__ void ldsm_x4(unsigned r[4], unsigned a) {
    asm volatile("ldmatrix.sync.aligned.m8n8.x4.shared.b16 {%0,%1,%2,%3}, [%4];"
                 : "=r"(r[0]), "=r"(r[1]), "=r"(r[2]), "=r"(r[3]) : "r"(a));
}
__device__ __forceinline__ void ldsm_x4t(unsigned r[4], unsigned a) {
    asm volatile("ldmatrix.sync.aligned.m8n8.x4.trans.shared.b16 {%0,%1,%2,%3}, [%4];"
                 : "=r"(r[0]), "=r"(r[1]), "=r"(r[2]), "=r"(r[3]) : "r"(a));
}
__device__ __forceinline__ void ldsm_x2t(unsigned r[2], unsigned a) {
    asm volatile("ldmatrix.sync.aligned.m8n8.x2.trans.shared.b16 {%0,%1}, [%2];"
                 : "=r"(r[0]), "=r"(r[1]) : "r"(a));
}
__device__ __forceinline__ void mma16816(float c[4], const unsigned a[4], const unsigned b0, const unsigned b1) {
    asm volatile("mma.sync.aligned.m16n8k16.row.col.f32.f16.f16.f32 "
                 "{%0,%1,%2,%3},{%4,%5,%6,%7},{%8,%9},{%0,%1,%2,%3};"
                 : "+f"(c[0]), "+f"(c[1]), "+f"(c[2]), "+f"(c[3])
                 : "r"(a[0]), "r"(a[1]), "r"(a[2]), "r"(a[3]), "r"(b0), "r"(b1));
}

__device__ __forceinline__ float gelu_exact(float v) {
    return 0.5f * v * (1.0f + erff(v * 0.70710678118654752f));
}

// ---------------- GEMM layer: C[16 rows per warp][128] = A @ W, bias+gelu, store half ----------------
template<int KSTEPS, int SA>
__device__ __forceinline__ void gemm_gelu_layer(
    const __half* __restrict__ Asm,          // stride SA halfs
    const __half* __restrict__ Wsm,          // stride 136 halfs, [K][128]
    const float*  __restrict__ bias,
    __half* __restrict__ Hout,               // stride 136 halfs
    int warp, int lane)
{
    const int m0 = warp * 16;
    float c[16][4];
#pragma unroll
    for (int n = 0; n < 16; n++) { c[n][0] = c[n][1] = c[n][2] = c[n][3] = 0.f; }

    const int arow = m0 + (lane & 15);
    const int acolofs = (lane >> 4) * 8;
    const int wrowlane = (lane & 15);

#pragma unroll
    for (int kk = 0; kk < KSTEPS; kk++) {
        unsigned a[4];
        ldsm_x4(a, smem_u32(Asm + arow * SA + kk * 16 + acolofs));
#pragma unroll
        for (int n2 = 0; n2 < 8; n2++) {
            unsigned b[4];
            ldsm_x4t(b, smem_u32(Wsm + (kk * 16 + wrowlane) * 136 + n2 * 16 + acolofs));
            mma16816(c[2 * n2],     a, b[0], b[1]);
            mma16816(c[2 * n2 + 1], a, b[2], b[3]);
        }
    }

    const int r0  = m0 + (lane >> 2);
    const int cc0 = (lane & 3) * 2;
#pragma unroll
    for (int n = 0; n < 16; n++) {
        int col = n * 8 + cc0;
        float bx = bias[col], by = bias[col + 1];
        float v0 = gelu_exact(c[n][0] + bx);
        float v1 = gelu_exact(c[n][1] + by);
        float v2 = gelu_exact(c[n][2] + bx);
        float v3 = gelu_exact(c[n][3] + by);
        *reinterpret_cast<__half2*>(Hout + r0 * 136 + col)       = __floats2half2_rn(v0, v1);
        *reinterpret_cast<__half2*>(Hout + (r0 + 8) * 136 + col) = __floats2half2_rn(v2, v3);
    }
}

// ---------------- main fused kernel ----------------
__global__ void __launch_bounds__(256, 1) hashmlp_kernel(
    const float* __restrict__ xg,
    const float* __restrict__ tabg,
    const float* __restrict__ W0g, const float* __restrict__ b0g,
    const float* __restrict__ W1g, const float* __restrict__ b1g,
    const float* __restrict__ W2g, const float* __restrict__ b2g,
    const float* __restrict__ W3g, const float* __restrict__ b3g,
    float* __restrict__ outg)
{
    extern __shared__ char smem_raw[];
    Smem& s = *reinterpret_cast<Smem*>(smem_raw);

    const int tid  = threadIdx.x;
    const int lane = tid & 31;
    const int warp = tid >> 5;

    // ---- load weights (once per persistent block) ----
    for (int i = tid; i < 32 * 128; i += 256)
        s.W0[i >> 7][i & 127] = __float2half(W0g[i]);
    for (int i = tid; i < 128 * 128; i += 256) {
        s.W1[i >> 7][i & 127] = __float2half(W1g[i]);
        s.W2[i >> 7][i & 127] = __float2half(W2g[i]);
    }
    for (int i = tid; i < 128 * 8; i += 256) {
        int k = i >> 3, n = i & 7;
        s.W3[k][n] = __float2half(n < 3 ? W3g[k * 3 + n] : 0.f);
    }
    for (int i = tid; i < 128; i += 256) {
        s.b0[i] = b0g[i]; s.b1[i] = b1g[i]; s.b2[i] = b2g[i];
    }
    if (tid < 4) s.b3[tid] = (tid < 3) ? b3g[tid] : 0.f;
    __syncthreads();

    const float2* __restrict__ xv = reinterpret_cast<const float2*>(xg);

    for (int tile = blockIdx.x; tile < NTILES; tile += gridDim.x) {
        const int gbase = tile * TILE_M;

        // ---- hash-grid encode: 2 threads per point, 8 levels each ----
        {
            const int p  = tid >> 1;           // warp w covers points 16w..16w+15 (its own MMA rows)
            const int lb = (tid & 1) * 8;
            float2 xy = __ldg(xv + gbase + p);
#pragma unroll
            for (int li = 0; li < 8; li++) {
                const int lvl = lb + li;
                const float r = c_res[lvl];
                float px = xy.x * r, py = xy.y * r;
                float fx = floorf(px), fy = floorf(py);
                float wx = px - fx,  wy = py - fy;
                unsigned ix = (unsigned)(int)fx;
                unsigned iy = (unsigned)(int)fy;
                const float2* tp = reinterpret_cast<const float2*>(tabg) + (size_t)lvl * TSZ;
                unsigned hy0 = iy * PRIME_Y;
                unsigned hy1 = (iy + 1u) * PRIME_Y;
                unsigned i00 = (ix        ^ hy0) & (TSZ - 1u);
                unsigned i01 = (ix        ^ hy1) & (TSZ - 1u);
                unsigned i10 = ((ix + 1u) ^ hy0) & (TSZ - 1u);
                unsigned i11 = ((ix + 1u) ^ hy1) & (TSZ - 1u);
                float2 f00 = __ldg(tp + i00);
                float2 f01 = __ldg(tp + i01);
                float2 f10 = __ldg(tp + i10);
                float2 f11 = __ldg(tp + i11);
                float w00 = (1.f - wx) * (1.f - wy);
                float w01 = (1.f - wx) * wy;
                float w10 = wx * (1.f - wy);
                float w11 = wx * wy;
                float e0 = f00.x * w00 + f01.x * w01 + f10.x * w10 + f11.x * w11;
                float e1 = f00.y * w00 + f01.y * w01 + f10.y * w10 + f11.y * w11;
                *reinterpret_cast<__half2*>(&s.A[p][2 * lvl]) = __floats2half2_rn(e0, e1);
            }
        }
        __syncwarp();

        // ---- MLP (all buffers row-partitioned per warp: no block barriers needed) ----
        gemm_gelu_layer<2, 40>(&s.A[0][0],  &s.W0[0][0], s.b0, &s.Ha[0][0], warp, lane);
        __syncwarp();
        gemm_gelu_layer<8, 136>(&s.Ha[0][0], &s.W1[0][0], s.b1, &s.Hb[0][0], warp, lane);
        __syncwarp();
        gemm_gelu_layer<8, 136>(&s.Hb[0][0], &s.W2[0][0], s.b2, &s.Ha[0][0], warp, lane);
        __syncwarp();

        // ---- output layer: Ha[128x128] @ W3pad[128x8] via one n-tile of MMA ----
        {
            const int m0 = warp * 16;
            float c[4] = {0.f, 0.f, 0.f, 0.f};
            const int arow = m0 + (lane & 15);
            const int acolofs = (lane >> 4) * 8;
#pragma unroll
            for (int kk = 0; kk < 8; kk++) {
                unsigned a[4];
                ldsm_x4(a, smem_u32(&s.Ha[0][0] + arow * 136 + kk * 16 + acolofs));
                unsigned b[2];
                ldsm_x2t(b, smem_u32(&s.W3[0][0] + (kk * 16 + (lane & 15)) * 8));
                mma16816(c, a, b[0], b[1]);
            }
            const int col = (lane & 3) * 2;
            const int r   = gbase + m0 + (lane >> 2);
            if (col == 0) {
                outg[(size_t)r * 3 + 0]       = c[0] + s.b3[0];
                outg[(size_t)r * 3 + 1]       = c[1] + s.b3[1];
                outg[(size_t)(r + 8) * 3 + 0] = c[2] + s.b3[0];
                outg[(size_t)(r + 8) * 3 + 1] = c[3] + s.b3[1];
            } else if (col == 2) {
                outg[(size_t)r * 3 + 2]       = c[0] + s.b3[2];
                outg[(size_t)(r + 8) * 3 + 2] = c[2] + s.b3[2];
            }
        }
        __syncwarp();   // before next tile overwrites A/Ha rows
    }
}

// ---------------- launch ----------------
extern "C" void kernel_launch(void* const* d_in, const int* in_sizes, int n_in,
                              void* d_out, int out_size)
{
    const float* xg  = (const float*)d_in[0];
    const float* tab = (const float*)d_in[1];
    const float* W0g = (const float*)d_in[2];
    const float* b0g = (const float*)d_in[3];
    const float* W1g = (const float*)d_in[4];
    const float* b1g = (const float*)d_in[5];
    const float* W2g = (const float*)d_in[6];
    const float* b2g = (const float*)d_in[7];
    const float* W3g = (const float*)d_in[8];
    const float* b3g = (const float*)d_in[9];
    float* outg = (float*)d_out;

    cudaFuncSetAttribute(hashmlp_kernel,
                         cudaFuncAttributeMaxDynamicSharedMemorySize,
                         (int)sizeof(Smem));
    hashmlp_kernel<<<148, 256, sizeof(Smem)>>>(
        xg, tab, W0g, b0g, W1g, b1g, W2g, b2g, W3g, b3g, outg);
}